// round 1
// baseline (speedup 1.0000x reference)
#include <cuda_runtime.h>

#define BATCH 32
#define HH 1024
#define WW 1024
#define WPR 32                        // 32-bit words per row
#define WORDS_PER_IMG (HH * WPR)      // 32768
#define NWORDS (BATCH * WORDS_PER_IMG) // 1048576 words = 4 MB
#define NCELLS (BATCH * HH * WW)      // 33554432

// Bit-packed scratch (graph rules forbid allocation; device globals are allowed)
__device__ unsigned g_A[NWORDS];
__device__ unsigned g_B[NWORDS];
__device__ unsigned g_T[NWORDS];
__device__ unsigned long long g_live;
__device__ unsigned long long g_mism;

__global__ void k_reset() {
    g_live = 0ull;
    g_mism = 0ull;
}

__global__ void k_pack_initial(const float* __restrict__ in) {
    int idx = blockIdx.x * blockDim.x + threadIdx.x;
    bool v = in[idx] > 0.5f;
    unsigned m = __ballot_sync(0xffffffffu, v);
    if ((threadIdx.x & 31) == 0) g_A[idx >> 5] = m;
}

// Copy target floats to output region AND pack target bits for the loss reduce.
__global__ void k_pack_target(const float* __restrict__ tgt, float* __restrict__ out_tgt) {
    int idx = blockIdx.x * blockDim.x + threadIdx.x;
    float f = tgt[idx];
    out_tgt[idx] = f;
    unsigned m = __ballot_sync(0xffffffffu, f > 0.5f);
    if ((threadIdx.x & 31) == 0) g_T[idx >> 5] = m;
}

__device__ __forceinline__ unsigned ld_word(const unsigned* __restrict__ img, int row, int wx) {
    // unsigned compare handles negative row/wx (zero-padded boundary)
    if ((unsigned)row >= (unsigned)HH || (unsigned)wx >= (unsigned)WPR) return 0u;
    return img[row * WPR + wx];
}

// Per-row horizontal 3-cell bit-sliced sum: h1:h0 = west + center + east per bit lane.
__device__ __forceinline__ void hsum(unsigned l, unsigned m, unsigned r,
                                     unsigned& h0, unsigned& h1) {
    unsigned L = __funnelshift_l(l, m, 1);  // west neighbor:  (m<<1)|(l>>31)
    unsigned R = __funnelshift_r(m, r, 1);  // east neighbor:  (m>>1)|(r<<31)
    unsigned t = L ^ R;
    h0 = t ^ m;
    h1 = (L & R) | (t & m);
}

template <bool A_TO_B>
__global__ void k_step() {
    int w = blockIdx.x * blockDim.x + threadIdx.x;
    const unsigned* __restrict__ src = A_TO_B ? g_A : g_B;
    unsigned* __restrict__ dst       = A_TO_B ? g_B : g_A;

    int b   = w >> 15;         // / WORDS_PER_IMG
    int ww  = w & 32767;
    int row = ww >> 5;
    int wx  = ww & 31;
    const unsigned* img = src + b * WORDS_PER_IMG;

    unsigned al = ld_word(img, row - 1, wx - 1), am = ld_word(img, row - 1, wx), ar = ld_word(img, row - 1, wx + 1);
    unsigned bl = ld_word(img, row,     wx - 1), bm = ld_word(img, row,     wx), br = ld_word(img, row,     wx + 1);
    unsigned cl = ld_word(img, row + 1, wx - 1), cm = ld_word(img, row + 1, wx), cr = ld_word(img, row + 1, wx + 1);

    unsigned h0a, h1a, h0b, h1b, h0c, h1c;
    hsum(al, am, ar, h0a, h1a);
    hsum(bl, bm, br, h0b, h1b);
    hsum(cl, cm, cr, h0c, h1c);

    // total 9-cell sum (includes self):
    // weight-1 bits: h0a + h0b + h0c -> s0 (w1), c1 (w2)
    unsigned t  = h0a ^ h0b;
    unsigned s0 = t ^ h0c;
    unsigned c1 = (h0a & h0b) | (t & h0c);
    // weight-2 bits: h1a + h1b + h1c + c1 -> s1 (w2), {q, c2} (w4)
    unsigned u  = h1a ^ h1b;
    unsigned p  = u ^ h1c;
    unsigned q  = (h1a & h1b) | (u & h1c);
    unsigned s1 = p ^ c1;
    unsigned c2 = p & c1;

    // next = (total==3) | (alive & total==4)
    unsigned eq3  = s0 & s1 & ~(q | c2);
    unsigned eq4  = (q ^ c2) & ~(s0 | s1);
    unsigned next = eq3 | (bm & eq4);

    dst[w] = next;
}

__global__ void k_unpack(float* __restrict__ out_state) {
    int idx = blockIdx.x * blockDim.x + threadIdx.x;
    unsigned word = g_A[idx >> 5];  // uniform per warp -> L1 broadcast
    out_state[idx] = ((word >> (threadIdx.x & 31)) & 1u) ? 1.0f : 0.0f;
}

// Popcount reduce over bit buffers: live = popc(S), mismatch = popc(S ^ T).
// error in {-1,0,1} so loss = mismatch / NCELLS and max_abs = mismatch ? 1 : 0.
__global__ void k_reduce() {
    __shared__ int sh_live[8], sh_mism[8];
    int i = blockIdx.x * blockDim.x + threadIdx.x;  // over NWORDS/4 uint4s
    const uint4* __restrict__ S = reinterpret_cast<const uint4*>(g_A);
    const uint4* __restrict__ T = reinterpret_cast<const uint4*>(g_T);
    uint4 s = S[i];
    uint4 tt = T[i];
    int live = __popc(s.x) + __popc(s.y) + __popc(s.z) + __popc(s.w);
    int mism = __popc(s.x ^ tt.x) + __popc(s.y ^ tt.y) + __popc(s.z ^ tt.z) + __popc(s.w ^ tt.w);
    #pragma unroll
    for (int o = 16; o > 0; o >>= 1) {
        live += __shfl_down_sync(0xffffffffu, live, o);
        mism += __shfl_down_sync(0xffffffffu, mism, o);
    }
    int lane = threadIdx.x & 31;
    int warp = threadIdx.x >> 5;
    if (lane == 0) { sh_live[warp] = live; sh_mism[warp] = mism; }
    __syncthreads();
    if (threadIdx.x == 0) {
        int L = 0, M = 0;
        #pragma unroll
        for (int k = 0; k < 8; ++k) { L += sh_live[k]; M += sh_mism[k]; }
        atomicAdd(&g_live, (unsigned long long)L);
        atomicAdd(&g_mism, (unsigned long long)M);
    }
}

__global__ void k_finalize(float* __restrict__ out) {
    unsigned long long mism = g_mism;
    out[0]              = (float)((double)mism / (double)NCELLS);          // loss
    out[1 + 2 * NCELLS] = (float)g_live;                                   // live_cells
    out[2 + 2 * NCELLS] = mism ? 1.0f : 0.0f;                              // max_abs_error
}

extern "C" void kernel_launch(void* const* d_in, const int* in_sizes, int n_in,
                              void* d_out, int out_size) {
    const float* initial = (const float*)d_in[0];
    const float* target  = (const float*)d_in[1];
    // d_in[2] = generations (fixed at 8 by the problem setup)
    (void)in_sizes; (void)n_in; (void)out_size;

    float* out       = (float*)d_out;
    float* out_state = out + 1;
    float* out_tgt   = out + 1 + NCELLS;

    const int TB = 256;

    k_reset<<<1, 1>>>();
    k_pack_initial<<<NCELLS / TB, TB>>>(initial);
    k_pack_target<<<NCELLS / TB, TB>>>(target, out_tgt);

    // 8 generations, ping-pong A <-> B; even count ends back in A.
    #pragma unroll
    for (int g = 0; g < 4; ++g) {
        k_step<true ><<<NWORDS / TB, TB>>>();
        k_step<false><<<NWORDS / TB, TB>>>();
    }

    k_unpack<<<NCELLS / TB, TB>>>(out_state);
    k_reduce<<<(NWORDS / 4) / TB, TB>>>();
    k_finalize<<<1, 1>>>(out);
}

// round 2
// speedup vs baseline: 2.5167x; 2.5167x over previous
#include <cuda_runtime.h>

#define BATCH 32
#define HH 1024
#define WW 1024
#define WPR 32                         // 32-bit words per row
#define WORDS_PER_IMG (HH * WPR)       // 32768
#define NWORDS (BATCH * WORDS_PER_IMG) // 1048576 words = 4 MB
#define NCELLS (BATCH * HH * WW)       // 33554432

// Bit-packed scratch (device globals; no allocation allowed)
__device__ unsigned g_A[NWORDS];   // packed initial state
__device__ unsigned g_B[NWORDS];   // packed final state (after 8 gens)
__device__ unsigned g_T[NWORDS];   // packed target
__device__ unsigned long long g_live;
__device__ unsigned long long g_mism;

__global__ void k_reset() { g_live = 0ull; g_mism = 0ull; }

// ---------------------------------------------------------------------------
// Pack BOTH inputs into bit buffers and copy target floats to the output
// region. Warp handles 256 consecutive cells (8 words). 8 coalesced loads per
// array per thread (MLP=8), ballot assembly, coalesced stores.
// ---------------------------------------------------------------------------
__global__ void k_pack(const float* __restrict__ ini, const float* __restrict__ tgt,
                       float* __restrict__ out_tgt) {
    int tid   = blockIdx.x * blockDim.x + threadIdx.x;
    int lane  = threadIdx.x & 31;
    int warp  = tid >> 5;
    unsigned cb = (unsigned)warp * 256u;   // cell base for this warp
    unsigned wb = (unsigned)warp * 8u;     // word base

    float fa[8], ft[8];
    #pragma unroll
    for (int k = 0; k < 8; ++k) fa[k] = ini[cb + 32u * k + lane];
    #pragma unroll
    for (int k = 0; k < 8; ++k) ft[k] = tgt[cb + 32u * k + lane];

    // copy target to output (coalesced 128B-per-warp stores)
    #pragma unroll
    for (int k = 0; k < 8; ++k) out_tgt[cb + 32u * k + lane] = ft[k];

    unsigned mywA = 0u, mywT = 0u;
    #pragma unroll
    for (int k = 0; k < 8; ++k) {
        unsigned bA = __ballot_sync(0xffffffffu, fa[k] > 0.5f);
        unsigned bT = __ballot_sync(0xffffffffu, ft[k] > 0.5f);
        if (lane == k) { mywA = bA; mywT = bT; }
    }
    if (lane < 8) {
        g_A[wb + lane] = mywA;
        g_T[wb + lane] = mywT;
    }
}

// ---------------------------------------------------------------------------
// Fused 8-generation Game of Life, bit-sliced, in shared memory.
// Tile: full row width (32 words) x 64 interior rows, 8-row halo top/bottom.
// Smem rows have guard word-columns at 0 and 33 (always zero).
// Validity shrinks 1 row/gen from the halo edges; interior [8,72) stays exact.
// ---------------------------------------------------------------------------
#define TH 64
#define SH (TH + 16)   // 80 smem rows
#define SW 34          // 32 data word cols + 2 guards

__device__ __forceinline__ void hsum(unsigned l, unsigned m, unsigned r,
                                     unsigned& h0, unsigned& h1) {
    unsigned L = __funnelshift_l(l, m, 1);  // west neighbors
    unsigned R = __funnelshift_r(m, r, 1);  // east neighbors
    unsigned t = L ^ R;
    h0 = t ^ m;
    h1 = (L & R) | (t & m);
}

__device__ __forceinline__ unsigned gol_combine(
    unsigned h0a, unsigned h1a, unsigned h0b, unsigned h1b,
    unsigned h0c, unsigned h1c, unsigned bm) {
    unsigned t  = h0a ^ h0b;
    unsigned s0 = t ^ h0c;
    unsigned c1 = (h0a & h0b) | (t & h0c);
    unsigned u  = h1a ^ h1b;
    unsigned p  = u ^ h1c;
    unsigned q  = (h1a & h1b) | (u & h1c);
    unsigned s1 = p ^ c1;
    unsigned c2 = p & c1;
    unsigned eq3 = s0 & s1 & ~(q | c2);          // total == 3
    unsigned eq4 = (q ^ c2) & ~(s0 | s1);        // total == 4
    return eq3 | (bm & eq4);
}

__global__ __launch_bounds__(256) void k_life8() {
    __shared__ unsigned sb[2][SH][SW];

    int tile = blockIdx.x;            // 512 tiles: 32 imgs x 16 vertical tiles
    int b    = tile >> 4;
    int ty   = tile & 15;
    int r0   = ty * TH;               // first interior global row
    int tid  = threadIdx.x;

    const unsigned* img = g_A + b * WORDS_PER_IMG;

    // zero guard columns (both buffers)
    for (int s = tid; s < SH; s += 256) {
        sb[0][s][0] = 0u; sb[0][s][33] = 0u;
        sb[1][s][0] = 0u; sb[1][s][33] = 0u;
    }
    // load tile + halo (zero outside image)
    for (int idx = tid; idx < SH * 32; idx += 256) {
        int s  = idx >> 5;
        int c  = idx & 31;
        int gr = r0 - 8 + s;
        unsigned v = ((unsigned)gr < (unsigned)HH) ? img[gr * WPR + c] : 0u;
        sb[0][s][c + 1] = v;
    }
    __syncthreads();

    int c      = tid & 31;            // word column (smem col c+1)
    int strip  = tid >> 5;            // 8 row strips
    int rstart = 1 + strip * 10;
    int rend   = (rstart + 10 < 79) ? (rstart + 10) : 79;  // exclusive

    #pragma unroll
    for (int g = 0; g < 8; ++g) {
        int cur = g & 1, nxt = cur ^ 1;

        unsigned h0a, h1a, h0b, h1b, h0c, h1c;
        // prime rows rstart-1 and rstart
        hsum(sb[cur][rstart - 1][c], sb[cur][rstart - 1][c + 1], sb[cur][rstart - 1][c + 2], h0a, h1a);
        unsigned bm = sb[cur][rstart][c + 1];
        hsum(sb[cur][rstart][c], bm, sb[cur][rstart][c + 2], h0b, h1b);

        for (int r = rstart; r < rend; ++r) {
            unsigned nl = sb[cur][r + 1][c];
            unsigned nm = sb[cur][r + 1][c + 1];
            unsigned nr = sb[cur][r + 1][c + 2];
            hsum(nl, nm, nr, h0c, h1c);

            unsigned next = gol_combine(h0a, h1a, h0b, h1b, h0c, h1c, bm);
            // force zero outside the image (global zero padding must persist)
            if ((unsigned)(r0 - 8 + r) >= (unsigned)HH) next = 0u;
            sb[nxt][r][c + 1] = next;

            h0a = h0b; h1a = h1b;
            h0b = h0c; h1b = h1c;
            bm  = nm;
        }
        __syncthreads();
    }

    // final state is in buffer 0 (8 gens: last write nxt=0); interior rows [8,72)
    unsigned* dst = g_B + b * WORDS_PER_IMG;
    for (int idx = tid; idx < TH * 32; idx += 256) {
        int s  = idx >> 5;
        int cc = idx & 31;
        dst[(r0 + s) * WPR + cc] = sb[0][8 + s][cc + 1];
    }
}

// ---------------------------------------------------------------------------
// Unpack final state to floats (coalesced) + fused popcount reduction.
// error in {-1,0,1}: loss = mismatches/N, max_abs = mism?1:0.
// ---------------------------------------------------------------------------
__global__ void k_unpack_reduce(float* __restrict__ out_state) {
    __shared__ int sh_live[8], sh_mism[8];
    int tid  = blockIdx.x * blockDim.x + threadIdx.x;
    int lane = threadIdx.x & 31;
    int warp = tid >> 5;
    unsigned cb = (unsigned)warp * 256u;
    unsigned wb = (unsigned)warp * 8u;

    unsigned ws[8], ts[8];
    #pragma unroll
    for (int k = 0; k < 8; ++k) ws[k] = g_B[wb + k];   // uniform -> broadcast
    #pragma unroll
    for (int k = 0; k < 8; ++k) ts[k] = g_T[wb + k];

    int live = 0, mism = 0;
    #pragma unroll
    for (int k = 0; k < 8; ++k) {
        unsigned bit  = (ws[k] >> lane) & 1u;
        unsigned tbit = (ts[k] >> lane) & 1u;
        out_state[cb + 32u * k + lane] = bit ? 1.0f : 0.0f;
        live += (int)bit;
        mism += (int)(bit ^ tbit);
    }
    #pragma unroll
    for (int o = 16; o > 0; o >>= 1) {
        live += __shfl_down_sync(0xffffffffu, live, o);
        mism += __shfl_down_sync(0xffffffffu, mism, o);
    }
    int w = threadIdx.x >> 5;
    if (lane == 0) { sh_live[w] = live; sh_mism[w] = mism; }
    __syncthreads();
    if (threadIdx.x == 0) {
        int L = 0, M = 0;
        #pragma unroll
        for (int k = 0; k < 8; ++k) { L += sh_live[k]; M += sh_mism[k]; }
        atomicAdd(&g_live, (unsigned long long)L);
        atomicAdd(&g_mism, (unsigned long long)M);
    }
}

__global__ void k_finalize(float* __restrict__ out) {
    unsigned long long mism = g_mism;
    out[0]              = (float)((double)mism / (double)NCELLS);  // loss
    out[1 + 2 * NCELLS] = (float)g_live;                           // live_cells
    out[2 + 2 * NCELLS] = mism ? 1.0f : 0.0f;                      // max_abs_error
}

extern "C" void kernel_launch(void* const* d_in, const int* in_sizes, int n_in,
                              void* d_out, int out_size) {
    const float* initial = (const float*)d_in[0];
    const float* target  = (const float*)d_in[1];
    (void)in_sizes; (void)n_in; (void)out_size;   // generations fixed at 8

    float* out       = (float*)d_out;
    float* out_state = out + 1;
    float* out_tgt   = out + 1 + NCELLS;

    const int TB = 256;

    k_reset<<<1, 1>>>();
    k_pack<<<NCELLS / (8 * TB), TB>>>(initial, target, out_tgt);
    k_life8<<<BATCH * (HH / TH), TB>>>();
    k_unpack_reduce<<<NCELLS / (8 * TB), TB>>>(out_state);
    k_finalize<<<1, 1>>>(out);
}

// round 3
// speedup vs baseline: 2.8807x; 1.1446x over previous
#include <cuda_runtime.h>

#define BATCH 32
#define HH 1024
#define WW 1024
#define WPR 32                         // 32-bit words per row
#define WORDS_PER_IMG (HH * WPR)       // 32768
#define NWORDS (BATCH * WORDS_PER_IMG) // 1048576 words = 4 MB
#define NCELLS (BATCH * HH * WW)       // 33554432

// Bit-packed scratch (device globals; no allocation allowed)
__device__ unsigned g_A[NWORDS];   // packed initial state
__device__ unsigned g_T[NWORDS];   // packed target
__device__ unsigned long long g_live;
__device__ unsigned long long g_mism;
__device__ unsigned g_done;

// ---------------------------------------------------------------------------
// Pack BOTH inputs into bit buffers, copy target floats to the output region,
// and reset the reduction counters (this kernel fully precedes k_life8 on the
// stream, so the resets are ordered before any atomics).
// ---------------------------------------------------------------------------
__global__ void k_pack(const float* __restrict__ ini, const float* __restrict__ tgt,
                       float* __restrict__ out_tgt) {
    if (blockIdx.x == 0 && threadIdx.x == 0) {
        g_live = 0ull; g_mism = 0ull; g_done = 0u;
    }
    int tid   = blockIdx.x * blockDim.x + threadIdx.x;
    int lane  = threadIdx.x & 31;
    int warp  = tid >> 5;
    unsigned cb = (unsigned)warp * 256u;   // cell base for this warp
    unsigned wb = (unsigned)warp * 8u;     // word base

    float fa[8], ft[8];
    #pragma unroll
    for (int k = 0; k < 8; ++k) fa[k] = ini[cb + 32u * k + lane];
    #pragma unroll
    for (int k = 0; k < 8; ++k) ft[k] = tgt[cb + 32u * k + lane];

    #pragma unroll
    for (int k = 0; k < 8; ++k) out_tgt[cb + 32u * k + lane] = ft[k];

    unsigned mywA = 0u, mywT = 0u;
    #pragma unroll
    for (int k = 0; k < 8; ++k) {
        unsigned bA = __ballot_sync(0xffffffffu, fa[k] > 0.5f);
        unsigned bT = __ballot_sync(0xffffffffu, ft[k] > 0.5f);
        if (lane == k) { mywA = bA; mywT = bT; }
    }
    if (lane < 8) {
        g_A[wb + lane] = mywA;
        g_T[wb + lane] = mywT;
    }
}

// ---------------------------------------------------------------------------
// Fused: 8 generations bit-sliced in smem  +  float unpack  +  popc reduction
// + last-block finalize. Tile: 32 words x 64 interior rows, 8-row halo.
// ---------------------------------------------------------------------------
#define TH 64
#define SH (TH + 16)   // 80 smem rows
#define SW 34          // 32 data word cols + 2 zero guards

__device__ __forceinline__ void hsum(unsigned l, unsigned m, unsigned r,
                                     unsigned& h0, unsigned& h1) {
    unsigned L = __funnelshift_l(l, m, 1);
    unsigned R = __funnelshift_r(m, r, 1);
    unsigned t = L ^ R;
    h0 = t ^ m;
    h1 = (L & R) | (t & m);
}

__device__ __forceinline__ unsigned gol_combine(
    unsigned h0a, unsigned h1a, unsigned h0b, unsigned h1b,
    unsigned h0c, unsigned h1c, unsigned bm) {
    unsigned t  = h0a ^ h0b;
    unsigned s0 = t ^ h0c;
    unsigned c1 = (h0a & h0b) | (t & h0c);
    unsigned u  = h1a ^ h1b;
    unsigned p  = u ^ h1c;
    unsigned q  = (h1a & h1b) | (u & h1c);
    unsigned s1 = p ^ c1;
    unsigned c2 = p & c1;
    unsigned eq3 = s0 & s1 & ~(q | c2);          // total == 3
    unsigned eq4 = (q ^ c2) & ~(s0 | s1);        // total == 4
    return eq3 | (bm & eq4);
}

__global__ __launch_bounds__(256) void k_life8(float* __restrict__ out) {
    __shared__ unsigned sb[2][SH][SW];
    __shared__ int sh_live[8], sh_mism[8];
    __shared__ int sh_last;

    int tile = blockIdx.x;            // 512 tiles: 32 imgs x 16 vertical tiles
    int b    = tile >> 4;
    int ty   = tile & 15;
    int r0   = ty * TH;               // first interior global row
    int tid  = threadIdx.x;

    const unsigned* img = g_A + b * WORDS_PER_IMG;

    for (int s = tid; s < SH; s += 256) {
        sb[0][s][0] = 0u; sb[0][s][33] = 0u;
        sb[1][s][0] = 0u; sb[1][s][33] = 0u;
    }
    for (int idx = tid; idx < SH * 32; idx += 256) {
        int s  = idx >> 5;
        int c  = idx & 31;
        int gr = r0 - 8 + s;
        unsigned v = ((unsigned)gr < (unsigned)HH) ? img[gr * WPR + c] : 0u;
        sb[0][s][c + 1] = v;
    }
    __syncthreads();

    int c      = tid & 31;
    int strip  = tid >> 5;
    int rstart = 1 + strip * 10;
    int rend   = (rstart + 10 < 79) ? (rstart + 10) : 79;

    #pragma unroll
    for (int g = 0; g < 8; ++g) {
        int cur = g & 1, nxt = cur ^ 1;

        unsigned h0a, h1a, h0b, h1b, h0c, h1c;
        hsum(sb[cur][rstart - 1][c], sb[cur][rstart - 1][c + 1], sb[cur][rstart - 1][c + 2], h0a, h1a);
        unsigned bm = sb[cur][rstart][c + 1];
        hsum(sb[cur][rstart][c], bm, sb[cur][rstart][c + 2], h0b, h1b);

        for (int r = rstart; r < rend; ++r) {
            unsigned nl = sb[cur][r + 1][c];
            unsigned nm = sb[cur][r + 1][c + 1];
            unsigned nr = sb[cur][r + 1][c + 2];
            hsum(nl, nm, nr, h0c, h1c);

            unsigned next = gol_combine(h0a, h1a, h0b, h1b, h0c, h1c, bm);
            if ((unsigned)(r0 - 8 + r) >= (unsigned)HH) next = 0u;  // keep outside zero
            sb[nxt][r][c + 1] = next;

            h0a = h0b; h1a = h1b;
            h0b = h0c; h1b = h1c;
            bm  = nm;
        }
        __syncthreads();
    }
    // final state: sb[0], interior smem rows [8, 72)

    // ---- reduction: popc over this tile's 2048 final words vs target ----
    const unsigned* tw = g_T + b * WORDS_PER_IMG + r0 * WPR;
    int live = 0, mism = 0;
    #pragma unroll
    for (int k = 0; k < 8; ++k) {
        int widx = tid + 256 * k;                  // 0..2047
        unsigned w = sb[0][8 + (widx >> 5)][(widx & 31) + 1];
        unsigned t = tw[widx];
        live += __popc(w);
        mism += __popc(w ^ t);
    }

    // ---- float expansion straight from smem (coalesced STG.32) ----
    // warp handles 8192 cells; per iter a warp writes 128 contiguous cells
    // (4 words, broadcast LDS), one bit per lane per word.
    int lane = tid & 31;
    int wrp  = tid >> 5;
    float* outp = out + 1 + ((size_t)b * HH + r0) * WW;   // out_state tile base
    #pragma unroll 4
    for (int k = 0; k < 64; ++k) {
        int cellbase = wrp * 8192 + k * 128;        // multiple of 128
        int wbase    = cellbase >> 5;               // 4 consecutive words
        #pragma unroll
        for (int j = 0; j < 4; ++j) {
            int widx = wbase + j;
            unsigned w = sb[0][8 + (widx >> 5)][(widx & 31) + 1];
            outp[cellbase + j * 32 + lane] =
                __uint_as_float(((w >> lane) & 1u) * 0x3f800000u);
        }
    }

    // ---- block reduce + atomics + last-block finalize ----
    #pragma unroll
    for (int o = 16; o > 0; o >>= 1) {
        live += __shfl_down_sync(0xffffffffu, live, o);
        mism += __shfl_down_sync(0xffffffffu, mism, o);
    }
    if (lane == 0) { sh_live[wrp] = live; sh_mism[wrp] = mism; }
    __syncthreads();
    if (tid == 0) {
        int L = 0, M = 0;
        #pragma unroll
        for (int k = 0; k < 8; ++k) { L += sh_live[k]; M += sh_mism[k]; }
        atomicAdd(&g_live, (unsigned long long)L);
        atomicAdd(&g_mism, (unsigned long long)M);
        __threadfence();
        unsigned prev = atomicAdd(&g_done, 1u);
        sh_last = (prev == (unsigned)(gridDim.x - 1)) ? 1 : 0;
    }
    __syncthreads();
    if (sh_last && tid == 0) {
        unsigned long long mism_t = g_mism;
        unsigned long long live_t = g_live;
        out[0]              = (float)((double)mism_t / (double)NCELLS);  // loss
        out[1 + 2 * NCELLS] = (float)live_t;                             // live_cells
        out[2 + 2 * NCELLS] = mism_t ? 1.0f : 0.0f;                      // max_abs_error
    }
}

extern "C" void kernel_launch(void* const* d_in, const int* in_sizes, int n_in,
                              void* d_out, int out_size) {
    const float* initial = (const float*)d_in[0];
    const float* target  = (const float*)d_in[1];
    (void)in_sizes; (void)n_in; (void)out_size;   // generations fixed at 8

    float* out     = (float*)d_out;
    float* out_tgt = out + 1 + NCELLS;

    const int TB = 256;
    k_pack<<<NCELLS / (8 * TB), TB>>>(initial, target, out_tgt);
    k_life8<<<BATCH * (HH / TH), TB>>>(out);
}